// round 4
// baseline (speedup 1.0000x reference)
#include <cuda_runtime.h>
#include <cuda_bf16.h>
#include <math.h>

// ---------------- problem constants ----------------
#define BATCH   8
#define SEQ     2048
#define TOK     (BATCH*SEQ)      // 16384
#define DMODEL  128
#define EMB     256
#define NLAYERS 3
#define NHEADS  8
#define HEADDIM 64
#define DSTATE  64
#define DCONV   4
#define DINNER  (NHEADS*HEADDIM)             // 512
#define DIP     (2*DINNER + 2*DSTATE + NHEADS) // 1160
#define CDIM    (DINNER + 2*DSTATE)          // 640
#define NFEAT   15

// ---------------- device scratch ----------------
__device__ float g_w[16];
__device__ float g_xn[TOK*EMB];
__device__ float g_x [TOK*EMB];
__device__ float g_z [TOK*DIP];
__device__ float g_xbc[TOK*CDIM];
__device__ float g_dt[TOK*NHEADS];
__device__ float g_dA[TOK*NHEADS];
__device__ float g_y [TOK*DINNER];
__device__ float g_h1[TOK*EMB];

// ---------------- helpers ----------------
__device__ __forceinline__ float blockReduceSum(float v) {
    __shared__ float red[32];
    int lane = threadIdx.x & 31;
    int wid  = threadIdx.x >> 5;
    int nw   = (blockDim.x + 31) >> 5;
    #pragma unroll
    for (int o = 16; o; o >>= 1) v += __shfl_xor_sync(0xffffffffu, v, o);
    __syncthreads();
    if (lane == 0) red[wid] = v;
    __syncthreads();
    float tot = 0.f;
    for (int i = 0; i < nw; ++i) tot += red[i];
    return tot;
}

__device__ __forceinline__ float siluf(float x) { return x / (1.f + expf(-x)); }

__device__ __forceinline__ void cp16(void* s, const void* g) {
    unsigned sa = (unsigned)__cvta_generic_to_shared(s);
    asm volatile("cp.async.ca.shared.global [%0], [%1], 16;\n" :: "r"(sa), "l"(g));
}
__device__ __forceinline__ void cp16z(void* s, const void* g, unsigned sz) {
    unsigned sa = (unsigned)__cvta_generic_to_shared(s);
    asm volatile("cp.async.ca.shared.global [%0], [%1], 16, %2;\n" :: "r"(sa), "l"(g), "r"(sz));
}
__device__ __forceinline__ void cp4(void* s, const void* g) {
    unsigned sa = (unsigned)__cvta_generic_to_shared(s);
    asm volatile("cp.async.ca.shared.global [%0], [%1], 4;\n" :: "r"(sa), "l"(g));
}
__device__ __forceinline__ void cp_commit() {
    asm volatile("cp.async.commit_group;\n" ::: "memory");
}
template<int N>
__device__ __forceinline__ void cp_wait() {
    asm volatile("cp.async.wait_group %0;\n" :: "n"(N) : "memory");
}

__device__ __forceinline__ void mma_tf32(float* d, const unsigned* a, unsigned b0, unsigned b1) {
    asm volatile(
        "mma.sync.aligned.m16n8k8.row.col.f32.tf32.tf32.f32 "
        "{%0,%1,%2,%3},{%4,%5,%6,%7},{%8,%9},{%0,%1,%2,%3};\n"
        : "+f"(d[0]), "+f"(d[1]), "+f"(d[2]), "+f"(d[3])
        : "r"(a[0]), "r"(a[1]), "r"(a[2]), "r"(a[3]), "r"(b0), "r"(b1));
}

// tf32 hi/lo split: hi = rna-truncated fp32 bit pattern (13 LSBs zero), exact
// residual lo = x - hi, itself converted to tf32. 3-MMA scheme recovers ~fp32.
__device__ __forceinline__ void tf32_split(float x, unsigned& hi, unsigned& lo) {
    unsigned h;
    asm("cvt.rna.tf32.f32 %0, %1;\n" : "=r"(h) : "f"(x));
    float r = x - __uint_as_float(h);
    unsigned l;
    asm("cvt.rna.tf32.f32 %0, %1;\n" : "=r"(l) : "f"(r));
    hi = h; lo = l;
}

// ---------------- K0: softmax of w_avg ----------------
__global__ void softmax_kernel(const float* __restrict__ wa, int n) {
    if (threadIdx.x == 0) {
        float mx = -1e30f;
        for (int i = 0; i < n; ++i) mx = fmaxf(mx, wa[i]);
        float s = 0.f;
        for (int i = 0; i < n; ++i) { float e = expf(wa[i] - mx); g_w[i] = e; s += e; }
        float inv = 1.f / s;
        for (int i = 0; i < n; ++i) g_w[i] *= inv;
    }
}

// ---------------- K1: weighted feature average + layernorm(128) ----------------
__global__ void __launch_bounds__(128) avg_ln_kernel(
    const float* __restrict__ feat, const float* __restrict__ lg,
    const float* __restrict__ lb) {
    int r = blockIdx.x;
    int d = threadIdx.x;
    float acc = 0.f;
    #pragma unroll
    for (int f = 0; f < NFEAT; ++f)
        acc = fmaf(g_w[f], feat[((size_t)f * TOK + r) * DMODEL + d], acc);
    float m = blockReduceSum(acc) * (1.f / DMODEL);
    float dv = acc - m;
    float var = blockReduceSum(dv * dv) * (1.f / DMODEL);
    g_xn[(size_t)r * DMODEL + d] = dv * rsqrtf(var + 1e-5f) * lg[d] + lb[d];
}

// ---------------- 3xTF32 tensor-core GEMM: C = A(MxK) @ W(KxN) + epi ----------------
// Tiles: BM=128 BN=128 BK=32, 256 threads = 8 warps (4m x 2n), warp tile 32x64.
// EPI: 0=none 1=+bias 2=gelu(x+bias) 3=+residual
#define AS_STRIDE 36
#define BS_STRIDE 132
#define AS_ELEMS (128*AS_STRIDE)
#define BS_ELEMS (32*BS_STRIDE)
#define TG_SMEM ((2*AS_ELEMS + 2*BS_ELEMS)*4)

template<int EPI>
__global__ void __launch_bounds__(256, 2) tgemm_kernel(
    const float* __restrict__ A, const float* __restrict__ W,
    const float* __restrict__ bias, const float* __restrict__ res,
    float* __restrict__ C, int M, int N, int K) {
    extern __shared__ float sm[];
    float* As[2] = { sm, sm + AS_ELEMS };
    float* Bs[2] = { sm + 2*AS_ELEMS, sm + 2*AS_ELEMS + BS_ELEMS };

    int tid = threadIdx.x;
    int n0 = blockIdx.x * 128;
    int m0 = blockIdx.y * 128;
    int wid = tid >> 5, lane = tid & 31;
    int wm = wid >> 1, wn = wid & 1;
    int m0w = wm * 32, n0w = wn * 64;
    int g = lane >> 2, q = lane & 3;

    float acc[2][8][4];
    #pragma unroll
    for (int mi = 0; mi < 2; ++mi)
        #pragma unroll
        for (int ni = 0; ni < 8; ++ni)
            #pragma unroll
            for (int c = 0; c < 4; ++c) acc[mi][ni][c] = 0.f;

    // load indices
    int ar = tid >> 1;              // 0..127
    int ak = (tid & 1) * 16;        // 0 or 16
    int bk = tid >> 3;              // 0..31
    int bn = (tid & 7) * 16;        // 0..112

    auto load_stage = [&](int buf, int k0) {
        const float* ag = A + (size_t)(m0 + ar) * K + k0 + ak;
        float* ad = As[buf] + ar * AS_STRIDE + ak;
        #pragma unroll
        for (int j = 0; j < 4; ++j) cp16(ad + j * 4, ag + j * 4);
        const float* bg = W + (size_t)(k0 + bk) * N + n0 + bn;
        float* bd = Bs[buf] + bk * BS_STRIDE + bn;
        #pragma unroll
        for (int j = 0; j < 4; ++j) {
            int col = n0 + bn + j * 4;
            int rem = N - col;
            unsigned sz = rem >= 4 ? 16u : (rem > 0 ? (unsigned)rem * 4u : 0u);
            cp16z(bd + j * 4, bg + j * 4, sz);
        }
    };

    int nk = K >> 5;
    load_stage(0, 0); cp_commit();
    load_stage(1, 32); cp_commit();

    for (int kb = 0; kb < nk; ++kb) {
        cp_wait<1>();
        __syncthreads();
        int buf = kb & 1;
        const float* Ab = As[buf];
        const float* Bb = Bs[buf];
        #pragma unroll
        for (int ks = 0; ks < 4; ++ks) {
            int kq = ks * 8;
            unsigned ah[2][4], al[2][4];
            #pragma unroll
            for (int mi = 0; mi < 2; ++mi) {
                const float* ab = Ab + (m0w + mi * 16 + g) * AS_STRIDE + kq + q;
                tf32_split(ab[0],                  ah[mi][0], al[mi][0]);
                tf32_split(ab[8 * AS_STRIDE],      ah[mi][1], al[mi][1]);
                tf32_split(ab[4],                  ah[mi][2], al[mi][2]);
                tf32_split(ab[8 * AS_STRIDE + 4],  ah[mi][3], al[mi][3]);
            }
            #pragma unroll
            for (int ni = 0; ni < 8; ++ni) {
                const float* bb = Bb + (kq + q) * BS_STRIDE + n0w + ni * 8 + g;
                unsigned bh0, bl0, bh1, bl1;
                tf32_split(bb[0],              bh0, bl0);
                tf32_split(bb[4 * BS_STRIDE],  bh1, bl1);
                // cross terms first, then hi*hi
                mma_tf32(acc[0][ni], al[0], bh0, bh1);
                mma_tf32(acc[1][ni], al[1], bh0, bh1);
                mma_tf32(acc[0][ni], ah[0], bl0, bl1);
                mma_tf32(acc[1][ni], ah[1], bl0, bl1);
                mma_tf32(acc[0][ni], ah[0], bh0, bh1);
                mma_tf32(acc[1][ni], ah[1], bh0, bh1);
            }
        }
        __syncthreads();
        if (kb + 2 < nk) load_stage(buf, (kb + 2) * 32);
        cp_commit();
    }

    // epilogue
    #pragma unroll
    for (int mi = 0; mi < 2; ++mi) {
        int row0 = m0 + m0w + mi * 16 + g;
        #pragma unroll
        for (int ni = 0; ni < 8; ++ni) {
            int col = n0 + n0w + ni * 8 + 2 * q;
            if (col >= N) continue;
            #pragma unroll
            for (int half = 0; half < 2; ++half) {
                int row = row0 + half * 8;
                float v0 = acc[mi][ni][half * 2 + 0];
                float v1 = acc[mi][ni][half * 2 + 1];
                if (EPI == 1) { v0 += bias[col]; v1 += bias[col + 1]; }
                else if (EPI == 2) {
                    v0 += bias[col]; v1 += bias[col + 1];
                    v0 = 0.5f * v0 * (1.f + erff(v0 * 0.70710678118654752f));
                    v1 = 0.5f * v1 * (1.f + erff(v1 * 0.70710678118654752f));
                } else if (EPI == 3) {
                    const float* rp = res + (size_t)row * N + col;
                    v0 += rp[0]; v1 += rp[1];
                }
                float2* cp = (float2*)(C + (size_t)row * N + col);
                *cp = make_float2(v0, v1);
            }
        }
    }
}

// ---------------- rmsnorm over EMB=256 ----------------
__global__ void __launch_bounds__(256) rmsnorm_kernel(
    const float* __restrict__ x, const float* __restrict__ w, float* __restrict__ o) {
    int r = blockIdx.x, e = threadIdx.x;
    float v = x[(size_t)r * EMB + e];
    float ss = blockReduceSum(v * v);
    o[(size_t)r * EMB + e] = v * rsqrtf(ss * (1.f / EMB) + 1e-5f) * w[e];
}

// ---------------- conv (depthwise causal, DCONV=4) + silu, plus dt/dA ----------------
__global__ void __launch_bounds__(256) conv_kernel(
    const float* __restrict__ cw, const float* __restrict__ cb,
    const float* __restrict__ dtb, const float* __restrict__ alog) {
    int r = blockIdx.x;
    int b = r >> 11, t = r & 2047;
    for (int c = threadIdx.x; c < CDIM; c += 256) {
        float acc = cb[c];
        #pragma unroll
        for (int k = 0; k < DCONV; ++k) {
            int tt = t - (DCONV - 1) + k;
            if (tt >= 0)
                acc = fmaf(g_z[((size_t)(b * SEQ + tt)) * DIP + DINNER + c], cw[c * DCONV + k], acc);
        }
        g_xbc[(size_t)r * CDIM + c] = siluf(acc);
    }
    if (threadIdx.x < NHEADS) {
        int hh = threadIdx.x;
        float v = g_z[(size_t)r * DIP + (DIP - NHEADS) + hh] + dtb[hh];
        float dt = (v > 20.f) ? v : log1pf(expf(v));
        g_dt[r * NHEADS + hh] = dt;
        g_dA[r * NHEADS + hh] = expf(-dt * expf(alog[hh]));
    }
}

// ---------------- selective scan ----------------
#define NS 8
struct __align__(16) Stage {
    float B[DSTATE]; float C[DSTATE]; float x[32]; float dt; float dA; float pad[2];
};

__global__ void __launch_bounds__(256) scan_kernel(const float* __restrict__ Dp) {
    int pz = blockIdx.x;
    int h  = blockIdx.y;
    int b  = blockIdx.z;
    __shared__ Stage st[NS];
    int tid = threadIdx.x;
    int pl = tid >> 3;
    int ng = tid & 7;
    float h0=0,h1=0,h2=0,h3=0,h4=0,h5=0,h6=0,h7=0;
    float Dv = Dp[h];

    auto issue = [&](int t) {
        const float* row = g_xbc + (size_t)(b * SEQ + t) * CDIM;
        Stage* s = &st[t & (NS - 1)];
        if (tid < 16)       cp16(&s->B[tid * 4], row + DINNER + tid * 4);
        else if (tid < 32)  cp16(&s->C[(tid - 16) * 4], row + DINNER + DSTATE + (tid - 16) * 4);
        else if (tid < 40)  cp16(&s->x[(tid - 32) * 4], row + h * HEADDIM + pz * 32 + (tid - 32) * 4);
        else if (tid == 40) cp4(&s->dt, g_dt + (size_t)(b * SEQ + t) * NHEADS + h);
        else if (tid == 41) cp4(&s->dA, g_dA + (size_t)(b * SEQ + t) * NHEADS + h);
    };

    #pragma unroll
    for (int t = 0; t < NS - 1; ++t) { issue(t); cp_commit(); }

    for (int t = 0; t < SEQ; ++t) {
        if (t + NS - 1 < SEQ) issue(t + NS - 1);
        cp_commit();
        cp_wait<NS - 2>();
        __syncthreads();
        Stage& s = st[t & (NS - 1)];
        float dtv = s.dt, dAv = s.dA;
        float xv = s.x[pl];
        float cbm = dtv * xv;
        float4 B0 = *(const float4*)(s.B + ng * 8);
        float4 B1 = *(const float4*)(s.B + ng * 8 + 4);
        float4 C0 = *(const float4*)(s.C + ng * 8);
        float4 C1 = *(const float4*)(s.C + ng * 8 + 4);
        float acc;
        h0 = fmaf(h0, dAv, cbm * B0.x); acc = h0 * C0.x;
        h1 = fmaf(h1, dAv, cbm * B0.y); acc = fmaf(h1, C0.y, acc);
        h2 = fmaf(h2, dAv, cbm * B0.z); acc = fmaf(h2, C0.z, acc);
        h3 = fmaf(h3, dAv, cbm * B0.w); acc = fmaf(h3, C0.w, acc);
        h4 = fmaf(h4, dAv, cbm * B1.x); acc = fmaf(h4, C1.x, acc);
        h5 = fmaf(h5, dAv, cbm * B1.y); acc = fmaf(h5, C1.y, acc);
        h6 = fmaf(h6, dAv, cbm * B1.z); acc = fmaf(h6, C1.z, acc);
        h7 = fmaf(h7, dAv, cbm * B1.w); acc = fmaf(h7, C1.w, acc);
        acc += __shfl_xor_sync(0xffffffffu, acc, 1);
        acc += __shfl_xor_sync(0xffffffffu, acc, 2);
        acc += __shfl_xor_sync(0xffffffffu, acc, 4);
        if (ng == 0)
            g_y[(size_t)(b * SEQ + t) * DINNER + h * HEADDIM + pz * 32 + pl] = acc + Dv * xv;
        __syncthreads();
    }
}

// ---------------- gating ----------------
__global__ void __launch_bounds__(256) gate_kernel(const float* __restrict__ gnw) {
    int r = blockIdx.x;
    float gs[2];
    float ss = 0.f;
    #pragma unroll
    for (int j = 0; j < 2; ++j) {
        int e = threadIdx.x + j * 256;
        float zz = g_z[(size_t)r * DIP + e];
        float yy = g_y[(size_t)r * DINNER + e];
        float gg = yy * siluf(zz);
        gs[j] = gg;
        ss += gg * gg;
    }
    ss = blockReduceSum(ss);
    float sc = rsqrtf(ss * (1.f / DINNER) + 1e-5f);
    #pragma unroll
    for (int j = 0; j < 2; ++j) {
        int e = threadIdx.x + j * 256;
        g_y[(size_t)r * DINNER + e] = gs[j] * sc * gnw[e];
    }
}

// ---------------- final norms ----------------
__global__ void __launch_bounds__(256) finalnorm_kernel(
    const float* __restrict__ rw, const float* __restrict__ lg, const float* __restrict__ lb) {
    int r = blockIdx.x, e = threadIdx.x;
    float v = g_x[(size_t)r * EMB + e];
    float ss = blockReduceSum(v * v);
    float xr = v * rsqrtf(ss * (1.f / EMB) + 1e-5f) * rw[e];
    float m = blockReduceSum(xr) * (1.f / EMB);
    float d = xr - m;
    float var = blockReduceSum(d * d) * (1.f / EMB);
    g_xn[(size_t)r * EMB + e] = d * rsqrtf(var + 1e-5f) * lg[e] + lb[e];
}

// ---------------- mlp2 ----------------
__global__ void __launch_bounds__(256) mlp2_kernel(
    const float* __restrict__ W2, const float* __restrict__ b2, float* __restrict__ out) {
    __shared__ float Ws[EMB * 5];
    __shared__ float bs[5];
    int tid = threadIdx.x;
    for (int i = tid; i < EMB * 5; i += 256) Ws[i] = W2[i];
    if (tid < 5) bs[tid] = b2[tid];
    __syncthreads();
    int warp = tid >> 5, lane = tid & 31;
    int tok = blockIdx.x * 8 + warp;
    float a0=0,a1=0,a2=0,a3=0,a4=0;
    for (int k = lane; k < EMB; k += 32) {
        float hv = g_h1[(size_t)tok * EMB + k];
        a0 = fmaf(hv, Ws[k * 5 + 0], a0);
        a1 = fmaf(hv, Ws[k * 5 + 1], a1);
        a2 = fmaf(hv, Ws[k * 5 + 2], a2);
        a3 = fmaf(hv, Ws[k * 5 + 3], a3);
        a4 = fmaf(hv, Ws[k * 5 + 4], a4);
    }
    #pragma unroll
    for (int o = 16; o; o >>= 1) {
        a0 += __shfl_xor_sync(0xffffffffu, a0, o);
        a1 += __shfl_xor_sync(0xffffffffu, a1, o);
        a2 += __shfl_xor_sync(0xffffffffu, a2, o);
        a3 += __shfl_xor_sync(0xffffffffu, a3, o);
        a4 += __shfl_xor_sync(0xffffffffu, a4, o);
    }
    if (lane == 0) {
        out[(size_t)tok * 5 + 0] = a0 + bs[0];
        out[(size_t)tok * 5 + 1] = a1 + bs[1];
        out[(size_t)tok * 5 + 2] = a2 + bs[2];
        out[(size_t)tok * 5 + 3] = a3 + bs[3];
        out[(size_t)tok * 5 + 4] = a4 + bs[4];
    }
}

// ---------------- host launcher ----------------
extern "C" void kernel_launch(void* const* d_in, const int* in_sizes, int n_in,
                              void* d_out, int out_size) {
    const float* feature     = (const float*)d_in[0];
    const float* w_avg       = (const float*)d_in[1];
    const float* inproj_ln_g = (const float*)d_in[2];
    const float* inproj_ln_b = (const float*)d_in[3];
    const float* inproj_W    = (const float*)d_in[4];
    const float* inproj_b    = (const float*)d_in[5];
    const float* rms_w       = (const float*)d_in[6];
    const float* m_inW       = (const float*)d_in[7];
    const float* m_convW     = (const float*)d_in[8];
    const float* m_convB     = (const float*)d_in[9];
    const float* m_dtb       = (const float*)d_in[10];
    const float* m_Alog      = (const float*)d_in[11];
    const float* m_D         = (const float*)d_in[12];
    const float* m_gnw       = (const float*)d_in[13];
    const float* m_outW      = (const float*)d_in[14];
    const float* norm_w      = (const float*)d_in[15];
    const float* mlp_ln_g    = (const float*)d_in[16];
    const float* mlp_ln_b    = (const float*)d_in[17];
    const float* mlp_W1      = (const float*)d_in[18];
    const float* mlp_b1      = (const float*)d_in[19];
    const float* mlp_W2      = (const float*)d_in[20];
    const float* mlp_b2      = (const float*)d_in[21];
    float* out = (float*)d_out;

    float *xn, *x, *z, *y, *h1;
    cudaGetSymbolAddress((void**)&xn, g_xn);
    cudaGetSymbolAddress((void**)&x,  g_x);
    cudaGetSymbolAddress((void**)&z,  g_z);
    cudaGetSymbolAddress((void**)&y,  g_y);
    cudaGetSymbolAddress((void**)&h1, g_h1);

    static bool attr_done = false;
    if (!attr_done) {
        cudaFuncSetAttribute(tgemm_kernel<0>, cudaFuncAttributeMaxDynamicSharedMemorySize, TG_SMEM);
        cudaFuncSetAttribute(tgemm_kernel<1>, cudaFuncAttributeMaxDynamicSharedMemorySize, TG_SMEM);
        cudaFuncSetAttribute(tgemm_kernel<2>, cudaFuncAttributeMaxDynamicSharedMemorySize, TG_SMEM);
        cudaFuncSetAttribute(tgemm_kernel<3>, cudaFuncAttributeMaxDynamicSharedMemorySize, TG_SMEM);
        attr_done = true;
    }

    softmax_kernel<<<1, 32>>>(w_avg, NFEAT);
    avg_ln_kernel<<<TOK, 128>>>(feature, inproj_ln_g, inproj_ln_b);
    // x = LN(feat_avg) @ inproj_W + inproj_b     (16384x128 @ 128x256)
    tgemm_kernel<1><<<dim3((EMB + 127) / 128, TOK / 128), 256, TG_SMEM>>>(
        xn, inproj_W, inproj_b, nullptr, x, TOK, EMB, DMODEL);

    for (int i = 0; i < NLAYERS; ++i) {
        rmsnorm_kernel<<<TOK, 256>>>(x, rms_w + (size_t)i * EMB, xn);
        // zxbcdt = xn @ m_inW[i]                 (16384x256 @ 256x1160)
        tgemm_kernel<0><<<dim3((DIP + 127) / 128, TOK / 128), 256, TG_SMEM>>>(
            xn, m_inW + (size_t)i * EMB * DIP, nullptr, nullptr, z, TOK, DIP, EMB);
        conv_kernel<<<TOK, 256>>>(m_convW + (size_t)i * CDIM * DCONV,
                                  m_convB + (size_t)i * CDIM,
                                  m_dtb + i * NHEADS, m_Alog + i * NHEADS);
        scan_kernel<<<dim3(2, NHEADS, BATCH), 256>>>(m_D + i * NHEADS);
        gate_kernel<<<TOK, 256>>>(m_gnw + (size_t)i * DINNER);
        // x = g @ m_outW[i] + x                  (16384x512 @ 512x256, residual)
        tgemm_kernel<3><<<dim3((EMB + 127) / 128, TOK / 128), 256, TG_SMEM>>>(
            y, m_outW + (size_t)i * DINNER * EMB, nullptr, x, x, TOK, EMB, DINNER);
    }

    finalnorm_kernel<<<TOK, 256>>>(norm_w, mlp_ln_g, mlp_ln_b);
    // h1 = gelu(xn @ W1 + b1)                    (16384x256 @ 256x256)
    tgemm_kernel<2><<<dim3((EMB + 127) / 128, TOK / 128), 256, TG_SMEM>>>(
        xn, mlp_W1, mlp_b1, nullptr, h1, TOK, EMB, EMB);
    mlp2_kernel<<<TOK / 8, 256>>>(mlp_W2, mlp_b2, out);
}

// round 5
// speedup vs baseline: 1.5388x; 1.5388x over previous
#include <cuda_runtime.h>
#include <cuda_bf16.h>
#include <math.h>

// ---------------- problem constants ----------------
#define BATCH   8
#define SEQ     2048
#define TOK     (BATCH*SEQ)      // 16384
#define DMODEL  128
#define EMB     256
#define NLAYERS 3
#define NHEADS  8
#define HEADDIM 64
#define DSTATE  64
#define DCONV   4
#define DINNER  (NHEADS*HEADDIM)             // 512
#define DIP     (2*DINNER + 2*DSTATE + NHEADS) // 1160
#define CDIM    (DINNER + 2*DSTATE)          // 640
#define NFEAT   15

// ---------------- device scratch ----------------
__device__ float g_w[16];
__device__ float g_xn[TOK*EMB];
__device__ float g_x [TOK*EMB];
__device__ float g_z [TOK*DIP];
__device__ float g_xbc[TOK*CDIM];
__device__ float2 g_dtA[TOK*NHEADS];   // (.x = dt, .y = dA)
__device__ float g_y [TOK*DINNER];
__device__ float g_h1[TOK*EMB];

// ---------------- helpers ----------------
__device__ __forceinline__ float blockReduceSum(float v) {
    __shared__ float red[32];
    int lane = threadIdx.x & 31;
    int wid  = threadIdx.x >> 5;
    int nw   = (blockDim.x + 31) >> 5;
    #pragma unroll
    for (int o = 16; o; o >>= 1) v += __shfl_xor_sync(0xffffffffu, v, o);
    __syncthreads();
    if (lane == 0) red[wid] = v;
    __syncthreads();
    float tot = 0.f;
    for (int i = 0; i < nw; ++i) tot += red[i];
    return tot;
}

__device__ __forceinline__ float siluf(float x) { return x / (1.f + expf(-x)); }

__device__ __forceinline__ void cp16(void* s, const void* g) {
    unsigned sa = (unsigned)__cvta_generic_to_shared(s);
    asm volatile("cp.async.ca.shared.global [%0], [%1], 16;\n" :: "r"(sa), "l"(g));
}
__device__ __forceinline__ void cp16z(void* s, const void* g, unsigned sz) {
    unsigned sa = (unsigned)__cvta_generic_to_shared(s);
    asm volatile("cp.async.ca.shared.global [%0], [%1], 16, %2;\n" :: "r"(sa), "l"(g), "r"(sz));
}
__device__ __forceinline__ void cp_commit() {
    asm volatile("cp.async.commit_group;\n" ::: "memory");
}
template<int N>
__device__ __forceinline__ void cp_wait() {
    asm volatile("cp.async.wait_group %0;\n" :: "n"(N) : "memory");
}

__device__ __forceinline__ void mma_tf32(float* d, const unsigned* a, unsigned b0, unsigned b1) {
    asm volatile(
        "mma.sync.aligned.m16n8k8.row.col.f32.tf32.tf32.f32 "
        "{%0,%1,%2,%3},{%4,%5,%6,%7},{%8,%9},{%0,%1,%2,%3};\n"
        : "+f"(d[0]), "+f"(d[1]), "+f"(d[2]), "+f"(d[3])
        : "r"(a[0]), "r"(a[1]), "r"(a[2]), "r"(a[3]), "r"(b0), "r"(b1));
}

__device__ __forceinline__ void tf32_split(float x, unsigned& hi, unsigned& lo) {
    unsigned h;
    asm("cvt.rna.tf32.f32 %0, %1;\n" : "=r"(h) : "f"(x));
    float r = x - __uint_as_float(h);
    unsigned l;
    asm("cvt.rna.tf32.f32 %0, %1;\n" : "=r"(l) : "f"(r));
    hi = h; lo = l;
}

// ---------------- K0: softmax of w_avg ----------------
__global__ void softmax_kernel(const float* __restrict__ wa, int n) {
    if (threadIdx.x == 0) {
        float mx = -1e30f;
        for (int i = 0; i < n; ++i) mx = fmaxf(mx, wa[i]);
        float s = 0.f;
        for (int i = 0; i < n; ++i) { float e = expf(wa[i] - mx); g_w[i] = e; s += e; }
        float inv = 1.f / s;
        for (int i = 0; i < n; ++i) g_w[i] *= inv;
    }
}

// ---------------- K1: weighted feature average + layernorm(128) ----------------
__global__ void __launch_bounds__(128) avg_ln_kernel(
    const float* __restrict__ feat, const float* __restrict__ lg,
    const float* __restrict__ lb) {
    int r = blockIdx.x;
    int d = threadIdx.x;
    float acc = 0.f;
    #pragma unroll
    for (int f = 0; f < NFEAT; ++f)
        acc = fmaf(g_w[f], feat[((size_t)f * TOK + r) * DMODEL + d], acc);
    float m = blockReduceSum(acc) * (1.f / DMODEL);
    float dv = acc - m;
    float var = blockReduceSum(dv * dv) * (1.f / DMODEL);
    g_xn[(size_t)r * DMODEL + d] = dv * rsqrtf(var + 1e-5f) * lg[d] + lb[d];
}

// ---------------- 3xTF32 tensor-core GEMM (unchanged from R4, passing) ----------------
#define AS_STRIDE 36
#define BS_STRIDE 132
#define AS_ELEMS (128*AS_STRIDE)
#define BS_ELEMS (32*BS_STRIDE)
#define TG_SMEM ((2*AS_ELEMS + 2*BS_ELEMS)*4)

template<int EPI>
__global__ void __launch_bounds__(256, 2) tgemm_kernel(
    const float* __restrict__ A, const float* __restrict__ W,
    const float* __restrict__ bias, const float* __restrict__ res,
    float* __restrict__ C, int M, int N, int K) {
    extern __shared__ float sm[];
    float* As[2] = { sm, sm + AS_ELEMS };
    float* Bs[2] = { sm + 2*AS_ELEMS, sm + 2*AS_ELEMS + BS_ELEMS };

    int tid = threadIdx.x;
    int n0 = blockIdx.x * 128;
    int m0 = blockIdx.y * 128;
    int wid = tid >> 5, lane = tid & 31;
    int wm = wid >> 1, wn = wid & 1;
    int m0w = wm * 32, n0w = wn * 64;
    int g = lane >> 2, q = lane & 3;

    float acc[2][8][4];
    #pragma unroll
    for (int mi = 0; mi < 2; ++mi)
        #pragma unroll
        for (int ni = 0; ni < 8; ++ni)
            #pragma unroll
            for (int c = 0; c < 4; ++c) acc[mi][ni][c] = 0.f;

    int ar = tid >> 1;
    int ak = (tid & 1) * 16;
    int bk = tid >> 3;
    int bn = (tid & 7) * 16;

    auto load_stage = [&](int buf, int k0) {
        const float* ag = A + (size_t)(m0 + ar) * K + k0 + ak;
        float* ad = As[buf] + ar * AS_STRIDE + ak;
        #pragma unroll
        for (int j = 0; j < 4; ++j) cp16(ad + j * 4, ag + j * 4);
        const float* bg = W + (size_t)(k0 + bk) * N + n0 + bn;
        float* bd = Bs[buf] + bk * BS_STRIDE + bn;
        #pragma unroll
        for (int j = 0; j < 4; ++j) {
            int col = n0 + bn + j * 4;
            int rem = N - col;
            unsigned sz = rem >= 4 ? 16u : (rem > 0 ? (unsigned)rem * 4u : 0u);
            cp16z(bd + j * 4, bg + j * 4, sz);
        }
    };

    int nk = K >> 5;
    load_stage(0, 0); cp_commit();
    load_stage(1, 32); cp_commit();

    for (int kb = 0; kb < nk; ++kb) {
        cp_wait<1>();
        __syncthreads();
        int buf = kb & 1;
        const float* Ab = As[buf];
        const float* Bb = Bs[buf];
        #pragma unroll
        for (int ks = 0; ks < 4; ++ks) {
            int kq = ks * 8;
            unsigned ah[2][4], al[2][4];
            #pragma unroll
            for (int mi = 0; mi < 2; ++mi) {
                const float* ab = Ab + (m0w + mi * 16 + g) * AS_STRIDE + kq + q;
                tf32_split(ab[0],                  ah[mi][0], al[mi][0]);
                tf32_split(ab[8 * AS_STRIDE],      ah[mi][1], al[mi][1]);
                tf32_split(ab[4],                  ah[mi][2], al[mi][2]);
                tf32_split(ab[8 * AS_STRIDE + 4],  ah[mi][3], al[mi][3]);
            }
            #pragma unroll
            for (int ni = 0; ni < 8; ++ni) {
                const float* bb = Bb + (kq + q) * BS_STRIDE + n0w + ni * 8 + g;
                unsigned bh0, bl0, bh1, bl1;
                tf32_split(bb[0],              bh0, bl0);
                tf32_split(bb[4 * BS_STRIDE],  bh1, bl1);
                mma_tf32(acc[0][ni], al[0], bh0, bh1);
                mma_tf32(acc[1][ni], al[1], bh0, bh1);
                mma_tf32(acc[0][ni], ah[0], bl0, bl1);
                mma_tf32(acc[1][ni], ah[1], bl0, bl1);
                mma_tf32(acc[0][ni], ah[0], bh0, bh1);
                mma_tf32(acc[1][ni], ah[1], bh0, bh1);
            }
        }
        __syncthreads();
        if (kb + 2 < nk) load_stage(buf, (kb + 2) * 32);
        cp_commit();
    }

    #pragma unroll
    for (int mi = 0; mi < 2; ++mi) {
        int row0 = m0 + m0w + mi * 16 + g;
        #pragma unroll
        for (int ni = 0; ni < 8; ++ni) {
            int col = n0 + n0w + ni * 8 + 2 * q;
            if (col >= N) continue;
            #pragma unroll
            for (int half = 0; half < 2; ++half) {
                int row = row0 + half * 8;
                float v0 = acc[mi][ni][half * 2 + 0];
                float v1 = acc[mi][ni][half * 2 + 1];
                if (EPI == 1) { v0 += bias[col]; v1 += bias[col + 1]; }
                else if (EPI == 2) {
                    v0 += bias[col]; v1 += bias[col + 1];
                    v0 = 0.5f * v0 * (1.f + erff(v0 * 0.70710678118654752f));
                    v1 = 0.5f * v1 * (1.f + erff(v1 * 0.70710678118654752f));
                } else if (EPI == 3) {
                    const float* rp = res + (size_t)row * N + col;
                    v0 += rp[0]; v1 += rp[1];
                }
                float2* cp = (float2*)(C + (size_t)row * N + col);
                *cp = make_float2(v0, v1);
            }
        }
    }
}

// ---------------- rmsnorm over EMB=256 ----------------
__global__ void __launch_bounds__(256) rmsnorm_kernel(
    const float* __restrict__ x, const float* __restrict__ w, float* __restrict__ o) {
    int r = blockIdx.x, e = threadIdx.x;
    float v = x[(size_t)r * EMB + e];
    float ss = blockReduceSum(v * v);
    o[(size_t)r * EMB + e] = v * rsqrtf(ss * (1.f / EMB) + 1e-5f) * w[e];
}

// ---------------- conv (depthwise causal, DCONV=4) + silu, plus packed dt/dA ----------------
__global__ void __launch_bounds__(256) conv_kernel(
    const float* __restrict__ cw, const float* __restrict__ cb,
    const float* __restrict__ dtb, const float* __restrict__ alog) {
    int r = blockIdx.x;
    int b = r >> 11, t = r & 2047;
    for (int c = threadIdx.x; c < CDIM; c += 256) {
        float acc = cb[c];
        #pragma unroll
        for (int k = 0; k < DCONV; ++k) {
            int tt = t - (DCONV - 1) + k;
            if (tt >= 0)
                acc = fmaf(g_z[((size_t)(b * SEQ + tt)) * DIP + DINNER + c], cw[c * DCONV + k], acc);
        }
        g_xbc[(size_t)r * CDIM + c] = siluf(acc);
    }
    if (threadIdx.x < NHEADS) {
        int hh = threadIdx.x;
        float v = g_z[(size_t)r * DIP + (DIP - NHEADS) + hh] + dtb[hh];
        float dt = (v > 20.f) ? v : log1pf(expf(v));
        float dA = expf(-dt * expf(alog[hh]));
        g_dtA[r * NHEADS + hh] = make_float2(dt, dA);
    }
}

// ---------------- selective scan: warp-autonomous, register state + register prefetch ----------------
// grid = (2, NHEADS, BATCH) = 128 CTAs, 256 threads.
// warp w owns p-rows [pz*32 + w*4, +4); lane = (p_sub = lane>>3, n_sub = lane&7);
// each lane: 1 p-row x 8 n-states in registers. No shared memory, no barriers.
#define SDEPTH 4

__global__ void __launch_bounds__(256) scan_kernel(const float* __restrict__ Dp) {
    int pz = blockIdx.x;
    int h  = blockIdx.y;
    int b  = blockIdx.z;
    int tid = threadIdx.x;
    int w = tid >> 5, lane = tid & 31;
    int p_sub = lane >> 3;      // 0..3
    int n_sub = lane & 7;       // 0..7  -> n = n_sub*8 .. +7
    int p = pz * 32 + w * 4 + p_sub;   // 0..63

    const float* base = g_xbc + (size_t)b * SEQ * CDIM;
    const float2* dbase = g_dtA + (size_t)b * SEQ * NHEADS + h;
    float* ybase = g_y + (size_t)b * SEQ * DINNER + h * HEADDIM + p;
    float Dv = Dp[h];

    float hs[8];
    #pragma unroll
    for (int j = 0; j < 8; ++j) hs[j] = 0.f;

    float4 Bb[SDEPTH][2], Cb[SDEPTH][2];
    float  xb[SDEPTH];
    float2 db[SDEPTH];

    const int boff = DINNER + n_sub * 8;
    const int coff = DINNER + DSTATE + n_sub * 8;
    const int xoff = h * HEADDIM + p;

    // prologue: fill the register ring
    #pragma unroll
    for (int s = 0; s < SDEPTH; ++s) {
        const float* row = base + (size_t)s * CDIM;
        Bb[s][0] = *(const float4*)(row + boff);
        Bb[s][1] = *(const float4*)(row + boff + 4);
        Cb[s][0] = *(const float4*)(row + coff);
        Cb[s][1] = *(const float4*)(row + coff + 4);
        xb[s] = row[xoff];
        db[s] = dbase[(size_t)s * NHEADS];
    }

    for (int t0 = 0; t0 < SEQ; t0 += SDEPTH) {
        #pragma unroll
        for (int s = 0; s < SDEPTH; ++s) {
            int t = t0 + s;
            float dtv = db[s].x, dAv = db[s].y;
            float xv = xb[s];
            float cbm = dtv * xv;
            float4 B0 = Bb[s][0], B1 = Bb[s][1];
            float4 C0 = Cb[s][0], C1 = Cb[s][1];
            float acc;
            hs[0] = fmaf(hs[0], dAv, cbm * B0.x); acc = hs[0] * C0.x;
            hs[1] = fmaf(hs[1], dAv, cbm * B0.y); acc = fmaf(hs[1], C0.y, acc);
            hs[2] = fmaf(hs[2], dAv, cbm * B0.z); acc = fmaf(hs[2], C0.z, acc);
            hs[3] = fmaf(hs[3], dAv, cbm * B0.w); acc = fmaf(hs[3], C0.w, acc);
            hs[4] = fmaf(hs[4], dAv, cbm * B1.x); acc = fmaf(hs[4], C1.x, acc);
            hs[5] = fmaf(hs[5], dAv, cbm * B1.y); acc = fmaf(hs[5], C1.y, acc);
            hs[6] = fmaf(hs[6], dAv, cbm * B1.z); acc = fmaf(hs[6], C1.z, acc);
            hs[7] = fmaf(hs[7], dAv, cbm * B1.w); acc = fmaf(hs[7], C1.w, acc);
            // reduce over the 8 lanes that share this p (lanes p_sub*8 .. +7)
            acc += __shfl_xor_sync(0xffffffffu, acc, 1);
            acc += __shfl_xor_sync(0xffffffffu, acc, 2);
            acc += __shfl_xor_sync(0xffffffffu, acc, 4);
            if (n_sub == 0)
                ybase[(size_t)t * DINNER] = acc + Dv * xv;
            // refill this ring slot with t + SDEPTH (clamped; tail values unused)
            int tn = t + SDEPTH;
            if (tn > SEQ - 1) tn = SEQ - 1;
            const float* row = base + (size_t)tn * CDIM;
            Bb[s][0] = *(const float4*)(row + boff);
            Bb[s][1] = *(const float4*)(row + boff + 4);
            Cb[s][0] = *(const float4*)(row + coff);
            Cb[s][1] = *(const float4*)(row + coff + 4);
            xb[s] = row[xoff];
            db[s] = dbase[(size_t)tn * NHEADS];
        }
    }
}

// ---------------- gating ----------------
__global__ void __launch_bounds__(256) gate_kernel(const float* __restrict__ gnw) {
    int r = blockIdx.x;
    float gs[2];
    float ss = 0.f;
    #pragma unroll
    for (int j = 0; j < 2; ++j) {
        int e = threadIdx.x + j * 256;
        float zz = g_z[(size_t)r * DIP + e];
        float yy = g_y[(size_t)r * DINNER + e];
        float gg = yy * siluf(zz);
        gs[j] = gg;
        ss += gg * gg;
    }
    ss = blockReduceSum(ss);
    float sc = rsqrtf(ss * (1.f / DINNER) + 1e-5f);
    #pragma unroll
    for (int j = 0; j < 2; ++j) {
        int e = threadIdx.x + j * 256;
        g_y[(size_t)r * DINNER + e] = gs[j] * sc * gnw[e];
    }
}

// ---------------- final norms ----------------
__global__ void __launch_bounds__(256) finalnorm_kernel(
    const float* __restrict__ rw, const float* __restrict__ lg, const float* __restrict__ lb) {
    int r = blockIdx.x, e = threadIdx.x;
    float v = g_x[(size_t)r * EMB + e];
    float ss = blockReduceSum(v * v);
    float xr = v * rsqrtf(ss * (1.f / EMB) + 1e-5f) * rw[e];
    float m = blockReduceSum(xr) * (1.f / EMB);
    float d = xr - m;
    float var = blockReduceSum(d * d) * (1.f / EMB);
    g_xn[(size_t)r * EMB + e] = d * rsqrtf(var + 1e-5f) * lg[e] + lb[e];
}

// ---------------- mlp2 ----------------
__global__ void __launch_bounds__(256) mlp2_kernel(
    const float* __restrict__ W2, const float* __restrict__ b2, float* __restrict__ out) {
    __shared__ float Ws[EMB * 5];
    __shared__ float bs[5];
    int tid = threadIdx.x;
    for (int i = tid; i < EMB * 5; i += 256) Ws[i] = W2[i];
    if (tid < 5) bs[tid] = b2[tid];
    __syncthreads();
    int warp = tid >> 5, lane = tid & 31;
    int tok = blockIdx.x * 8 + warp;
    float a0=0,a1=0,a2=0,a3=0,a4=0;
    for (int k = lane; k < EMB; k += 32) {
        float hv = g_h1[(size_t)tok * EMB + k];
        a0 = fmaf(hv, Ws[k * 5 + 0], a0);
        a1 = fmaf(hv, Ws[k * 5 + 1], a1);
        a2 = fmaf(hv, Ws[k * 5 + 2], a2);
        a3 = fmaf(hv, Ws[k * 5 + 3], a3);
        a4 = fmaf(hv, Ws[k * 5 + 4], a4);
    }
    #pragma unroll
    for (int o = 16; o; o >>= 1) {
        a0 += __shfl_xor_sync(0xffffffffu, a0, o);
        a1 += __shfl_xor_sync(0xffffffffu, a1, o);
        a2 += __shfl_xor_sync(0xffffffffu, a2, o);
        a3 += __shfl_xor_sync(0xffffffffu, a3, o);
        a4 += __shfl_xor_sync(0xffffffffu, a4, o);
    }
    if (lane == 0) {
        out[(size_t)tok * 5 + 0] = a0 + bs[0];
        out[(size_t)tok * 5 + 1] = a1 + bs[1];
        out[(size_t)tok * 5 + 2] = a2 + bs[2];
        out[(size_t)tok * 5 + 3] = a3 + bs[3];
        out[(size_t)tok * 5 + 4] = a4 + bs[4];
    }
}

// ---------------- host launcher ----------------
extern "C" void kernel_launch(void* const* d_in, const int* in_sizes, int n_in,
                              void* d_out, int out_size) {
    const float* feature     = (const float*)d_in[0];
    const float* w_avg       = (const float*)d_in[1];
    const float* inproj_ln_g = (const float*)d_in[2];
    const float* inproj_ln_b = (const float*)d_in[3];
    const float* inproj_W    = (const float*)d_in[4];
    const float* inproj_b    = (const float*)d_in[5];
    const float* rms_w       = (const float*)d_in[6];
    const float* m_inW       = (const float*)d_in[7];
    const float* m_convW     = (const float*)d_in[8];
    const float* m_convB     = (const float*)d_in[9];
    const float* m_dtb       = (const float*)d_in[10];
    const float* m_Alog      = (const float*)d_in[11];
    const float* m_D         = (const float*)d_in[12];
    const float* m_gnw       = (const float*)d_in[13];
    const float* m_outW      = (const float*)d_in[14];
    const float* norm_w      = (const float*)d_in[15];
    const float* mlp_ln_g    = (const float*)d_in[16];
    const float* mlp_ln_b    = (const float*)d_in[17];
    const float* mlp_W1      = (const float*)d_in[18];
    const float* mlp_b1      = (const float*)d_in[19];
    const float* mlp_W2      = (const float*)d_in[20];
    const float* mlp_b2      = (const float*)d_in[21];
    float* out = (float*)d_out;

    float *xn, *x, *z, *y, *h1;
    cudaGetSymbolAddress((void**)&xn, g_xn);
    cudaGetSymbolAddress((void**)&x,  g_x);
    cudaGetSymbolAddress((void**)&z,  g_z);
    cudaGetSymbolAddress((void**)&y,  g_y);
    cudaGetSymbolAddress((void**)&h1, g_h1);

    static bool attr_done = false;
    if (!attr_done) {
        cudaFuncSetAttribute(tgemm_kernel<0>, cudaFuncAttributeMaxDynamicSharedMemorySize, TG_SMEM);
        cudaFuncSetAttribute(tgemm_kernel<1>, cudaFuncAttributeMaxDynamicSharedMemorySize, TG_SMEM);
        cudaFuncSetAttribute(tgemm_kernel<2>, cudaFuncAttributeMaxDynamicSharedMemorySize, TG_SMEM);
        cudaFuncSetAttribute(tgemm_kernel<3>, cudaFuncAttributeMaxDynamicSharedMemorySize, TG_SMEM);
        attr_done = true;
    }

    softmax_kernel<<<1, 32>>>(w_avg, NFEAT);
    avg_ln_kernel<<<TOK, 128>>>(feature, inproj_ln_g, inproj_ln_b);
    // x = LN(feat_avg) @ inproj_W + inproj_b     (16384x128 @ 128x256)
    tgemm_kernel<1><<<dim3((EMB + 127) / 128, TOK / 128), 256, TG_SMEM>>>(
        xn, inproj_W, inproj_b, nullptr, x, TOK, EMB, DMODEL);

    for (int i = 0; i < NLAYERS; ++i) {
        rmsnorm_kernel<<<TOK, 256>>>(x, rms_w + (size_t)i * EMB, xn);
        // zxbcdt = xn @ m_inW[i]                 (16384x256 @ 256x1160)
        tgemm_kernel<0><<<dim3((DIP + 127) / 128, TOK / 128), 256, TG_SMEM>>>(
            xn, m_inW + (size_t)i * EMB * DIP, nullptr, nullptr, z, TOK, DIP, EMB);
        conv_kernel<<<TOK, 256>>>(m_convW + (size_t)i * CDIM * DCONV,
                                  m_convB + (size_t)i * CDIM,
                                  m_dtb + i * NHEADS, m_Alog + i * NHEADS);
        scan_kernel<<<dim3(2, NHEADS, BATCH), 256>>>(m_D + i * NHEADS);
        gate_kernel<<<TOK, 256>>>(m_gnw + (size_t)i * DINNER);
        // x = g @ m_outW[i] + x                  (16384x512 @ 512x256, residual)
        tgemm_kernel<3><<<dim3((EMB + 127) / 128, TOK / 128), 256, TG_SMEM>>>(
            y, m_outW + (size_t)i * DINNER * EMB, nullptr, x, x, TOK, EMB, DINNER);
    }

    finalnorm_kernel<<<TOK, 256>>>(norm_w, mlp_ln_g, mlp_ln_b);
    // h1 = gelu(xn @ W1 + b1)                    (16384x256 @ 256x256)
    tgemm_kernel<2><<<dim3((EMB + 127) / 128, TOK / 128), 256, TG_SMEM>>>(
        xn, mlp_W1, mlp_b1, nullptr, h1, TOK, EMB, EMB);
    mlp2_kernel<<<TOK / 8, 256>>>(mlp_W2, mlp_b2, out);
}